// round 14
// baseline (speedup 1.0000x reference)
#include <cuda_runtime.h>
#include <cuda_bf16.h>
#include <cstdint>

// ---------------- problem constants ----------------
#define B_ROWS 1024
#define DIM    192
#define NCLS   100000

#define TN  128                        // classes per CTA tile
#define RB  64                         // rows per inner block
#define NRB (B_ROWS / RB)              // 16
#define NT  ((NCLS + TN - 1) / TN)     // 782 tiles
#define NOOR ((float)(NT * TN - NCLS)) // 96 out-of-range cols -> each row sum += 96*exp2(0)
#define NKB (DIM / 16)                 // 12 k16-steps
#define STR 200                        // smem row stride in bf16 elems (400B)
#define STRB (STR * 2)                 // 400 bytes

#define S_SCALE 30.0f
#define LOG2E_F 1.4426950408889634f
#define SLOG2E  (S_SCALE * LOG2E_F)
#define COS_M_C 0.98006657784124163f
#define SIN_M_C 0.19866933079506122f
#define TH_C    (-0.98006657784124163f)
#define MM_C    0.039733866159012244f

// ---------------- smem layout (bytes): exactly 76800 -> 3 CTAs/SM ----------------
#define WS_OFF   0                       // W tile: 128 rows x 400B = 51200
#define WS_SZ    (TN * STRB)
#define XS_OFF   (WS_OFF + WS_SZ)        // X block: 64 rows x 400B = 25600 (single buf)
#define XS_SZ    (RB * STRB)
#define SMEM_TOTAL (XS_OFF + XS_SZ)      // 76800

// ---------------- scratch (device globals; no allocation) ----------------
__device__ float              g_rowsum[B_ROWS];
__device__ unsigned long long g_rowmax[B_ROWS];
__device__ float              g_label_t[B_ROWS];
__device__ __nv_bfloat16      g_xbf[B_ROWS * DIM];        // normalized x, bf16
__device__ __nv_bfloat16      g_wbf[(size_t)NCLS * DIM];  // w rounded to bf16
__device__ float              g_ascale[NCLS];             // S*log2e / ||w_bf16||
__device__ int                g_lbl[B_ROWS];              // labels as int32
__device__ int                g_lab64;

// ---------------- helpers ----------------
__device__ __forceinline__ uint32_t smem_u32(const void* p) {
    uint32_t a;
    asm("{ .reg .u64 t; cvta.to.shared.u64 t, %1; cvt.u32.u64 %0, t; }" : "=r"(a) : "l"(p));
    return a;
}
__device__ __forceinline__ float ex2_fast(float x) {   // single MUFU.EX2
    float r;
    asm("ex2.approx.ftz.f32 %0, %1;" : "=f"(r) : "f"(x));
    return r;
}
__device__ __forceinline__ float sqrt_fast(float x) {
    float r;
    asm("sqrt.approx.ftz.f32 %0, %1;" : "=f"(r) : "f"(x));
    return r;
}
#define CP_ASYNC16(dst, src) \
    asm volatile("cp.async.cg.shared.global [%0], [%1], 16;" :: "r"(dst), "l"(src) : "memory")
#define CP_COMMIT() asm volatile("cp.async.commit_group;" ::: "memory")
#define CP_WAIT0()  asm volatile("cp.async.wait_group 0;" ::: "memory")

#define LDSM4(r0, r1, r2, r3, a) \
    asm volatile("ldmatrix.sync.aligned.m8n8.x4.shared.b16 {%0,%1,%2,%3}, [%4];" \
                 : "=r"(r0), "=r"(r1), "=r"(r2), "=r"(r3) : "r"(a))

__device__ __forceinline__ void mma_bf16(float* d, const uint32_t* a, const uint32_t* b) {
    asm volatile(
        "mma.sync.aligned.m16n8k16.row.col.f32.bf16.bf16.f32 "
        "{%0,%1,%2,%3}, {%4,%5,%6,%7}, {%8,%9}, {%0,%1,%2,%3};"
        : "+f"(d[0]), "+f"(d[1]), "+f"(d[2]), "+f"(d[3])
        : "r"(a[0]), "r"(a[1]), "r"(a[2]), "r"(a[3]), "r"(b[0]), "r"(b[1]));
}
__device__ __forceinline__ unsigned int fkey(float v) {
    unsigned int u = __float_as_uint(v);
    return (u & 0x80000000u) ? ~u : (u | 0x80000000u);
}
__device__ __forceinline__ int load_label(const void* lp, int i, int is64) {
    if (is64) return (int)(((const long long*)lp)[i]);
    return ((const int*)lp)[i];
}

// ---------------- kernel 0a: detect label dtype ----------------
__global__ void detect_kernel(const int* __restrict__ lw) {
    __shared__ int any;
    if (threadIdx.x == 0) any = 0;
    __syncthreads();
    int i = threadIdx.x;
    if (i < 512 && lw[2 * i + 1] != 0) atomicOr(&any, 1);
    __syncthreads();
    if (threadIdx.x == 0) g_lab64 = (any == 0) ? 1 : 0;
}

// ---------------- kernel 0b: normalize x -> bf16, labels -> int32, zero scratch ---
__global__ void prep_x_kernel(const float* __restrict__ x, const void* __restrict__ label) {
    int b = blockIdx.x, k = threadIdx.x;  // 192 threads
    float v = x[b * DIM + k];
    float ss = v * v;
    #pragma unroll
    for (int o = 16; o > 0; o >>= 1) ss += __shfl_xor_sync(0xffffffffu, ss, o);
    __shared__ float wp[6];
    __shared__ float inv_s;
    if ((k & 31) == 0) wp[k >> 5] = ss;
    __syncthreads();
    if (k == 0) {
        float t = 0.f;
        #pragma unroll
        for (int i = 0; i < 6; i++) t += wp[i];
        inv_s = 1.0f / fmaxf(sqrtf(t), 1e-12f);
        g_rowsum[b] = 0.f;
        g_rowmax[b] = 0ull;
        g_lbl[b] = load_label(label, b, g_lab64);
    }
    __syncthreads();
    g_xbf[b * DIM + k] = __float2bfloat16(v * inv_s);
}

// ---------------- kernel 0c: w -> bf16 + per-class combined scale ----------------
__global__ void prep_w_kernel(const float* __restrict__ wgt) {
    int c = blockIdx.x * 4 + (threadIdx.x >> 5);  // 1 class per warp
    int l = threadIdx.x & 31;
    if (c >= NCLS) return;
    const float* wr = wgt + (size_t)c * DIM;
    __nv_bfloat16* wo = g_wbf + (size_t)c * DIM;
    float ss = 0.f;
    #pragma unroll
    for (int i = 0; i < 6; i++) {
        float v = wr[l * 6 + i];
        __nv_bfloat16 bv = __float2bfloat16(v);
        float vb = __bfloat162float(bv);
        ss += vb * vb;
        wo[l * 6 + i] = bv;
    }
    #pragma unroll
    for (int o = 16; o > 0; o >>= 1) ss += __shfl_xor_sync(0xffffffffu, ss, o);
    if (l == 0) g_ascale[c] = (ss > 0.f) ? SLOG2E * rsqrtf(ss) : 0.f;
}

// ---------------- kernel 1: bf16 HMMA GEMM + fused margin/softmax epilogue --------
__global__ void __launch_bounds__(256, 3)
gemm_epi_kernel() {
    extern __shared__ char smem[];
    const uint32_t sb = smem_u32(smem);
    const int tid = threadIdx.x;
    const int warp = tid >> 5, lane = tid & 31;
    const int c0 = blockIdx.x * TN;

    // W tile + X block 0 via cp.async (24 x 16B chunks per 192-elem row)
    for (int i = tid; i < TN * 24; i += 256) {
        int c = i / 24, j = i % 24;
        int cg = c0 + c; if (cg >= NCLS) cg = NCLS - 1;  // clamp (asv=0 kills OOR cols)
        CP_ASYNC16(sb + WS_OFF + c * STRB + j * 16,
                   (const char*)g_wbf + (size_t)cg * (DIM * 2) + j * 16);
    }
    for (int i = tid; i < RB * 24; i += 256) {
        int r = i / 24, j = i % 24;
        CP_ASYNC16(sb + XS_OFF + r * STRB + j * 16,
                   (const char*)g_xbf + (size_t)r * (DIM * 2) + j * 16);
    }
    CP_COMMIT();

    // warp grid: 2 (rows) x 4 (cols); each warp: 32 rows x 32 cols
    const int wm = warp >> 2, wn = warp & 3;
    const int g = lane >> 2, tig = lane & 3;

    // per-thread class scales (block-invariant): 8 cols; OOR -> 0 so t=0, exp2=1
    // (each row sum gains exactly NOOR=96; finalize subtracts it)
    float asv[4][2];
    #pragma unroll
    for (int ni = 0; ni < 4; ni++)
        #pragma unroll
        for (int q = 0; q < 2; q++) {
            int c = c0 + wn * 32 + ni * 8 + tig * 2 + q;
            asv[ni][q] = (c < NCLS) ? __ldg(&g_ascale[c]) : 0.f;
        }

    // ldmatrix lane address components
    const int a_row = wm * 32 + (lane & 7) + ((lane >> 3) & 1) * 8;
    const uint32_t a_koff = ((lane >> 4) & 1) * 16;  // bytes
    const uint32_t xa0 = sb + XS_OFF + a_row * STRB + a_koff;
    const uint32_t xa1 = xa0 + 16 * STRB;

    const int b_mat = lane >> 3;
    const int b_row = wn * 32 + (b_mat >> 1) * 8 + (lane & 7);
    const uint32_t b_koff = (b_mat & 1) * 16;  // bytes
    uint32_t b_addr[2];
    #pragma unroll
    for (int p = 0; p < 2; p++)
        b_addr[p] = sb + WS_OFF + (b_row + p * 16) * STRB + b_koff;

    CP_WAIT0();
    __syncthreads();

    for (int blk = 0; blk < NRB; blk++) {
        float acc[2][4][4];
        #pragma unroll
        for (int mi = 0; mi < 2; mi++)
            #pragma unroll
            for (int ni = 0; ni < 4; ni++)
                #pragma unroll
                for (int q = 0; q < 4; q++) acc[mi][ni][q] = 0.f;

        #pragma unroll
        for (int kb = 0; kb < NKB; kb++) {
            const uint32_t kadd = kb * 32;  // 16 bf16 = 32 bytes
            uint32_t af[2][4];
            LDSM4(af[0][0], af[0][1], af[0][2], af[0][3], xa0 + kadd);
            LDSM4(af[1][0], af[1][1], af[1][2], af[1][3], xa1 + kadd);
            uint32_t bf[4][2];
            #pragma unroll
            for (int p = 0; p < 2; p++)
                LDSM4(bf[2 * p][0], bf[2 * p][1], bf[2 * p + 1][0], bf[2 * p + 1][1],
                      b_addr[p] + kadd);
            #pragma unroll
            for (int mi = 0; mi < 2; mi++)
                #pragma unroll
                for (int ni = 0; ni < 4; ni++)
                    mma_bf16(acc[mi][ni], af[mi], bf[ni]);
        }

        // all warps done reading X -> start next X load; epilogue overlaps it
        if (blk + 1 < NRB) {
            __syncthreads();
            for (int i = tid; i < RB * 24; i += 256) {
                int r = i / 24, j = i % 24;
                CP_ASYNC16(sb + XS_OFF + r * STRB + j * 16,
                           (const char*)g_xbf + ((size_t)(blk + 1) * RB + r) * (DIM * 2) + j * 16);
            }
            CP_COMMIT();
        }

        // fused epilogue. Per (mi,half) row:
        //  1. rare path: if the label lands in this thread's 8 columns, apply the
        //     margin by rewriting that acc element (so the clean loop sees it).
        //  2. clean loop: t=acc*asv; e=ex2(t); psum+=e; integer-max on e-bits with a
        //     5-bit (tig,ni,q) payload in the clobbered low mantissa bits.
        #pragma unroll
        for (int mi = 0; mi < 2; mi++) {
            #pragma unroll
            for (int half = 0; half < 2; half++) {
                int row = blk * RB + wm * 32 + mi * 16 + g + half * 8;
                int lab = __ldg(&g_lbl[row]);
                int rel = lab - c0;
                bool mine = ((unsigned)rel < (unsigned)TN) && ((rel >> 5) == wn) &&
                            (((rel >> 1) & 3) == tig);
                if (mine) {
                    int nl = (rel >> 3) & 3, ql = rel & 1;
                    float t = acc[mi][nl][half * 2 + ql] * asv[nl][ql];
                    float cs = t * (1.0f / SLOG2E);
                    float sn = sqrt_fast(fmaxf(1.0f - cs * cs, 0.f));
                    float ph = cs * COS_M_C - sn * SIN_M_C;
                    if (!(cs - TH_C > 0.f)) ph = cs - MM_C;
                    float tn = ph * SLOG2E;
                    g_label_t[row] = tn;                       // unique writer per row
                    acc[mi][nl][half * 2 + ql] = tn / asv[nl][ql];  // rare exact div
                }
                float psum = 0.f;
                uint32_t kmax = 0u;
                #pragma unroll
                for (int ni = 0; ni < 4; ni++) {
                    #pragma unroll
                    for (int q = 0; q < 2; q++) {
                        float t = acc[mi][ni][half * 2 + q] * asv[ni][q];
                        float e = ex2_fast(t);
                        psum += e;
                        uint32_t key = (__float_as_uint(e) & ~31u) |
                                       ((uint32_t)tig << 3) | ((uint32_t)ni << 1) | (uint32_t)q;
                        kmax = (key > kmax) ? key : kmax;
                    }
                }
                psum += __shfl_xor_sync(0xffffffffu, psum, 1);
                psum += __shfl_xor_sync(0xffffffffu, psum, 2);
                uint32_t o;
                o = __shfl_xor_sync(0xffffffffu, kmax, 1); kmax = (o > kmax) ? o : kmax;
                o = __shfl_xor_sync(0xffffffffu, kmax, 2); kmax = (o > kmax) ? o : kmax;
                if (tig == (int)((kmax >> 3) & 3)) {   // winning lane: exact global key
                    int ni = (kmax >> 1) & 3, q = kmax & 1;
                    float t = acc[mi][ni][half * 2 + q] * asv[ni][q];
                    int c = c0 + wn * 32 + ni * 8 + tig * 2 + q;
                    unsigned long long key64 =
                        ((unsigned long long)fkey(t) << 32) |
                        (unsigned long long)(0xFFFFFFFFu - (unsigned)c);
                    atomicMax(&g_rowmax[row], key64);
                }
                if (tig == 0) atomicAdd(&g_rowsum[row], psum);
            }
        }

        if (blk + 1 < NRB) {
            CP_WAIT0();
            __syncthreads();
        }
    }
}

// ---------------- kernel 2: finalize loss + prec1 ----------------
__global__ void finalize_kernel(float* __restrict__ out, int out_n) {
    __shared__ float sl[B_ROWS];
    __shared__ int   sh[B_ROWS];
    int b = threadIdx.x;
    float s = g_rowsum[b] - NOOR;  // remove the 96 exp2(0)=1 dummy-column terms
    float loss_b = (log2f(s) - g_label_t[b]) * 0.6931471805599453f;
    unsigned int idx = 0xFFFFFFFFu - (unsigned int)(g_rowmax[b] & 0xFFFFFFFFull);
    int lab = g_lbl[b];
    sl[b] = loss_b;
    sh[b] = (idx == (unsigned int)lab) ? 1 : 0;
    __syncthreads();
    for (int st = B_ROWS / 2; st > 0; st >>= 1) {
        if (b < st) { sl[b] += sl[b + st]; sh[b] += sh[b + st]; }
        __syncthreads();
    }
    if (b == 0) {
        out[0] = sl[0] * (1.0f / B_ROWS);
        if (out_n > 1) out[1] = (float)sh[0] * (100.0f / B_ROWS);
    }
}

// ---------------- launch ----------------
extern "C" void kernel_launch(void* const* d_in, const int* in_sizes, int n_in,
                              void* d_out, int out_size) {
    const float* x   = (const float*)d_in[0];
    const float* wgt = (const float*)d_in[1];
    const void*  lab = d_in[2];
    float* out = (float*)d_out;
    (void)in_sizes; (void)n_in;

    cudaFuncSetAttribute(gemm_epi_kernel, cudaFuncAttributeMaxDynamicSharedMemorySize,
                         SMEM_TOTAL);
    cudaFuncSetAttribute(gemm_epi_kernel, cudaFuncAttributePreferredSharedMemoryCarveout,
                         100);

    detect_kernel<<<1, 1024>>>((const int*)lab);
    prep_x_kernel<<<B_ROWS, DIM>>>(x, lab);
    prep_w_kernel<<<(NCLS + 3) / 4, 128>>>(wgt);
    gemm_epi_kernel<<<NT, 256, SMEM_TOTAL>>>();
    finalize_kernel<<<1, B_ROWS>>>(out, out_size);
}

// round 15
// speedup vs baseline: 1.3353x; 1.3353x over previous
#include <cuda_runtime.h>
#include <cuda_bf16.h>
#include <cstdint>

// ---------------- problem constants ----------------
#define B_ROWS 1024
#define DIM    192
#define NCLS   100000

#define TN  128                        // classes per CTA tile
#define RB  64                         // rows per inner block
#define NRB (B_ROWS / RB)              // 16
#define NT  ((NCLS + TN - 1) / TN)     // 782 tiles
#define NOOR ((float)(NT * TN - NCLS)) // 96 out-of-range cols -> each row sum += 96*exp2(0)
#define NKB (DIM / 16)                 // 12 k16-steps
#define STR 200                        // smem row stride in bf16 elems (400B)
#define STRB (STR * 2)                 // 400 bytes

#define S_SCALE 30.0f
#define LOG2E_F 1.4426950408889634f
#define SLOG2E  (S_SCALE * LOG2E_F)
#define COS_M_C 0.98006657784124163f
#define SIN_M_C 0.19866933079506122f
#define TH_C    (-0.98006657784124163f)
#define MM_C    0.039733866159012244f

// ---------------- smem layout (bytes): exactly 76800 -> 3 CTAs/SM ----------------
#define WS_OFF   0                       // W tile: 128 rows x 400B = 51200
#define WS_SZ    (TN * STRB)
#define XS_OFF   (WS_OFF + WS_SZ)        // X block: 64 rows x 400B = 25600 (single buf)
#define XS_SZ    (RB * STRB)
#define SMEM_TOTAL (XS_OFF + XS_SZ)      // 76800

// ---------------- scratch (device globals; no allocation) ----------------
__device__ float              g_rowsum[B_ROWS];
__device__ unsigned long long g_rowmax[B_ROWS];
__device__ float              g_label_t[B_ROWS];
__device__ __nv_bfloat16      g_xbf[B_ROWS * DIM];        // normalized x, bf16
__device__ __nv_bfloat16      g_wbf[(size_t)NCLS * DIM];  // w rounded to bf16
__device__ float              g_ascale[NCLS];             // S*log2e / ||w_bf16||
__device__ int                g_lbl[B_ROWS];              // labels as int32
__device__ int                g_lab64;

// ---------------- helpers ----------------
__device__ __forceinline__ uint32_t smem_u32(const void* p) {
    uint32_t a;
    asm("{ .reg .u64 t; cvta.to.shared.u64 t, %1; cvt.u32.u64 %0, t; }" : "=r"(a) : "l"(p));
    return a;
}
__device__ __forceinline__ float ex2_fast(float x) {   // single MUFU.EX2
    float r;
    asm("ex2.approx.ftz.f32 %0, %1;" : "=f"(r) : "f"(x));
    return r;
}
__device__ __forceinline__ float sqrt_fast(float x) {
    float r;
    asm("sqrt.approx.ftz.f32 %0, %1;" : "=f"(r) : "f"(x));
    return r;
}
#define CP_ASYNC16(dst, src) \
    asm volatile("cp.async.cg.shared.global [%0], [%1], 16;" :: "r"(dst), "l"(src) : "memory")
#define CP_COMMIT() asm volatile("cp.async.commit_group;" ::: "memory")
#define CP_WAIT0()  asm volatile("cp.async.wait_group 0;" ::: "memory")

#define LDSM4(r0, r1, r2, r3, a) \
    asm volatile("ldmatrix.sync.aligned.m8n8.x4.shared.b16 {%0,%1,%2,%3}, [%4];" \
                 : "=r"(r0), "=r"(r1), "=r"(r2), "=r"(r3) : "r"(a))

__device__ __forceinline__ void mma_bf16(float* d, const uint32_t* a, const uint32_t* b) {
    asm volatile(
        "mma.sync.aligned.m16n8k16.row.col.f32.bf16.bf16.f32 "
        "{%0,%1,%2,%3}, {%4,%5,%6,%7}, {%8,%9}, {%0,%1,%2,%3};"
        : "+f"(d[0]), "+f"(d[1]), "+f"(d[2]), "+f"(d[3])
        : "r"(a[0]), "r"(a[1]), "r"(a[2]), "r"(a[3]), "r"(b[0]), "r"(b[1]));
}
__device__ __forceinline__ unsigned int fkey(float v) {
    unsigned int u = __float_as_uint(v);
    return (u & 0x80000000u) ? ~u : (u | 0x80000000u);
}
__device__ __forceinline__ int load_label(const void* lp, int i, int is64) {
    if (is64) return (int)(((const long long*)lp)[i]);
    return ((const int*)lp)[i];
}

// ---------------- kernel 0a: detect label dtype ----------------
__global__ void detect_kernel(const int* __restrict__ lw) {
    __shared__ int any;
    if (threadIdx.x == 0) any = 0;
    __syncthreads();
    int i = threadIdx.x;
    if (i < 512 && lw[2 * i + 1] != 0) atomicOr(&any, 1);
    __syncthreads();
    if (threadIdx.x == 0) g_lab64 = (any == 0) ? 1 : 0;
}

// ---------------- kernel 0b: normalize x -> bf16, labels -> int32, zero scratch ---
__global__ void prep_x_kernel(const float* __restrict__ x, const void* __restrict__ label) {
    int b = blockIdx.x, k = threadIdx.x;  // 192 threads
    float v = x[b * DIM + k];
    float ss = v * v;
    #pragma unroll
    for (int o = 16; o > 0; o >>= 1) ss += __shfl_xor_sync(0xffffffffu, ss, o);
    __shared__ float wp[6];
    __shared__ float inv_s;
    if ((k & 31) == 0) wp[k >> 5] = ss;
    __syncthreads();
    if (k == 0) {
        float t = 0.f;
        #pragma unroll
        for (int i = 0; i < 6; i++) t += wp[i];
        inv_s = 1.0f / fmaxf(sqrtf(t), 1e-12f);
        g_rowsum[b] = 0.f;
        g_rowmax[b] = 0ull;
        g_lbl[b] = load_label(label, b, g_lab64);
    }
    __syncthreads();
    g_xbf[b * DIM + k] = __float2bfloat16(v * inv_s);
}

// ---------------- kernel 0c: w -> bf16 + per-class combined scale ----------------
__global__ void prep_w_kernel(const float* __restrict__ wgt) {
    int c = blockIdx.x * 4 + (threadIdx.x >> 5);  // 1 class per warp
    int l = threadIdx.x & 31;
    if (c >= NCLS) return;
    const float* wr = wgt + (size_t)c * DIM;
    __nv_bfloat16* wo = g_wbf + (size_t)c * DIM;
    float ss = 0.f;
    #pragma unroll
    for (int i = 0; i < 6; i++) {
        float v = wr[l * 6 + i];
        __nv_bfloat16 bv = __float2bfloat16(v);
        float vb = __bfloat162float(bv);
        ss += vb * vb;
        wo[l * 6 + i] = bv;
    }
    #pragma unroll
    for (int o = 16; o > 0; o >>= 1) ss += __shfl_xor_sync(0xffffffffu, ss, o);
    if (l == 0) g_ascale[c] = (ss > 0.f) ? SLOG2E * rsqrtf(ss) : 0.f;
}

// ---------------- kernel 1: bf16 HMMA GEMM + fused margin/softmax epilogue --------
__global__ void __launch_bounds__(256, 3)
gemm_epi_kernel() {
    extern __shared__ char smem[];
    const uint32_t sb = smem_u32(smem);
    const int tid = threadIdx.x;
    const int warp = tid >> 5, lane = tid & 31;
    const int c0 = blockIdx.x * TN;

    // W tile + X block 0 via cp.async (24 x 16B chunks per 192-elem row)
    for (int i = tid; i < TN * 24; i += 256) {
        int c = i / 24, j = i % 24;
        int cg = c0 + c; if (cg >= NCLS) cg = NCLS - 1;  // clamp (asv=0 kills OOR cols)
        CP_ASYNC16(sb + WS_OFF + c * STRB + j * 16,
                   (const char*)g_wbf + (size_t)cg * (DIM * 2) + j * 16);
    }
    for (int i = tid; i < RB * 24; i += 256) {
        int r = i / 24, j = i % 24;
        CP_ASYNC16(sb + XS_OFF + r * STRB + j * 16,
                   (const char*)g_xbf + (size_t)r * (DIM * 2) + j * 16);
    }
    CP_COMMIT();

    // warp grid: 2 (rows) x 4 (cols); each warp: 32 rows x 32 cols
    const int wm = warp >> 2, wn = warp & 3;
    const int g = lane >> 2, tig = lane & 3;

    // per-thread class scales (block-invariant): 8 cols; OOR -> 0 so t=0, exp2=1
    // (each row sum gains exactly NOOR=96; finalize subtracts it)
    float asv[4][2];
    #pragma unroll
    for (int ni = 0; ni < 4; ni++)
        #pragma unroll
        for (int q = 0; q < 2; q++) {
            int c = c0 + wn * 32 + ni * 8 + tig * 2 + q;
            asv[ni][q] = (c < NCLS) ? __ldg(&g_ascale[c]) : 0.f;
        }

    // ldmatrix lane address components
    const int a_row = wm * 32 + (lane & 7) + ((lane >> 3) & 1) * 8;
    const uint32_t a_koff = ((lane >> 4) & 1) * 16;  // bytes
    const uint32_t xa0 = sb + XS_OFF + a_row * STRB + a_koff;
    const uint32_t xa1 = xa0 + 16 * STRB;

    const int b_mat = lane >> 3;
    const int b_row = wn * 32 + (b_mat >> 1) * 8 + (lane & 7);
    const uint32_t b_koff = (b_mat & 1) * 16;  // bytes
    uint32_t b_addr[2];
    #pragma unroll
    for (int p = 0; p < 2; p++)
        b_addr[p] = sb + WS_OFF + (b_row + p * 16) * STRB + b_koff;

    CP_WAIT0();
    __syncthreads();

    for (int blk = 0; blk < NRB; blk++) {
        float acc[2][4][4];
        #pragma unroll
        for (int mi = 0; mi < 2; mi++)
            #pragma unroll
            for (int ni = 0; ni < 4; ni++)
                #pragma unroll
                for (int q = 0; q < 4; q++) acc[mi][ni][q] = 0.f;

        #pragma unroll
        for (int kb = 0; kb < NKB; kb++) {
            const uint32_t kadd = kb * 32;  // 16 bf16 = 32 bytes
            uint32_t af[2][4];
            LDSM4(af[0][0], af[0][1], af[0][2], af[0][3], xa0 + kadd);
            LDSM4(af[1][0], af[1][1], af[1][2], af[1][3], xa1 + kadd);
            uint32_t bf[4][2];
            #pragma unroll
            for (int p = 0; p < 2; p++)
                LDSM4(bf[2 * p][0], bf[2 * p][1], bf[2 * p + 1][0], bf[2 * p + 1][1],
                      b_addr[p] + kadd);
            #pragma unroll
            for (int mi = 0; mi < 2; mi++)
                #pragma unroll
                for (int ni = 0; ni < 4; ni++)
                    mma_bf16(acc[mi][ni], af[mi], bf[ni]);
        }

        // all warps done reading X -> start next X load; epilogue overlaps it
        if (blk + 1 < NRB) {
            __syncthreads();
            for (int i = tid; i < RB * 24; i += 256) {
                int r = i / 24, j = i % 24;
                CP_ASYNC16(sb + XS_OFF + r * STRB + j * 16,
                           (const char*)g_xbf + ((size_t)(blk + 1) * RB + r) * (DIM * 2) + j * 16);
            }
            CP_COMMIT();
        }

        // fused epilogue. Per (mi,half) row:
        //  1. rare branch (taken ~1/783 thread-rows): apply margin to the label acc
        //     element via STATIC-indexed unrolled selection (keeps acc in registers).
        //  2. clean loop (no label check): t=acc*asv; e=ex2(t); psum+=e; integer max
        //     on e-bits with 5-bit (tig,ni,q) payload in clobbered low mantissa bits.
        //  3. winning lane reconstructs exact t via STATIC-indexed unrolled compare
        //     and issues the exact 64-bit global atomicMax key.
        #pragma unroll
        for (int mi = 0; mi < 2; mi++) {
            #pragma unroll
            for (int half = 0; half < 2; half++) {
                int row = blk * RB + wm * 32 + mi * 16 + g + half * 8;
                int lab = __ldg(&g_lbl[row]);
                int rel = lab - c0;
                bool mine = ((unsigned)rel < (unsigned)TN) && ((rel >> 5) == wn) &&
                            (((rel >> 1) & 3) == tig);
                if (mine) {
                    int wni = (rel >> 3) & 3, wq = rel & 1;
                    #pragma unroll
                    for (int ni = 0; ni < 4; ni++)
                        #pragma unroll
                        for (int q = 0; q < 2; q++)
                            if (wni == ni && wq == q) {   // static acc index
                                float t = acc[mi][ni][half * 2 + q] * asv[ni][q];
                                float cs = t * (1.0f / SLOG2E);
                                float sn = sqrt_fast(fmaxf(1.0f - cs * cs, 0.f));
                                float ph = cs * COS_M_C - sn * SIN_M_C;
                                if (!(cs - TH_C > 0.f)) ph = cs - MM_C;
                                float tn = ph * SLOG2E;
                                g_label_t[row] = tn;                     // unique writer
                                acc[mi][ni][half * 2 + q] = tn / asv[ni][q];
                            }
                }
                float psum = 0.f;
                uint32_t kmax = 0u;
                #pragma unroll
                for (int ni = 0; ni < 4; ni++) {
                    #pragma unroll
                    for (int q = 0; q < 2; q++) {
                        float t = acc[mi][ni][half * 2 + q] * asv[ni][q];
                        float e = ex2_fast(t);
                        psum += e;
                        uint32_t key = (__float_as_uint(e) & ~31u) |
                                       ((uint32_t)tig << 3) | ((uint32_t)(ni << 1) | q);
                        kmax = (key > kmax) ? key : kmax;
                    }
                }
                psum += __shfl_xor_sync(0xffffffffu, psum, 1);
                psum += __shfl_xor_sync(0xffffffffu, psum, 2);
                uint32_t o;
                o = __shfl_xor_sync(0xffffffffu, kmax, 1); kmax = (o > kmax) ? o : kmax;
                o = __shfl_xor_sync(0xffffffffu, kmax, 2); kmax = (o > kmax) ? o : kmax;
                if (tig == (int)((kmax >> 3) & 3)) {   // winning lane
                    int wni = (kmax >> 1) & 3, wq = kmax & 1;
                    float tbest = 0.f;
                    int cbest = 0;
                    #pragma unroll
                    for (int ni = 0; ni < 4; ni++)
                        #pragma unroll
                        for (int q = 0; q < 2; q++)
                            if (wni == ni && wq == q) {   // static acc index
                                tbest = acc[mi][ni][half * 2 + q] * asv[ni][q];
                                cbest = c0 + wn * 32 + ni * 8 + tig * 2 + q;
                            }
                    unsigned long long key64 =
                        ((unsigned long long)fkey(tbest) << 32) |
                        (unsigned long long)(0xFFFFFFFFu - (unsigned)cbest);
                    atomicMax(&g_rowmax[row], key64);
                }
                if (tig == 0) atomicAdd(&g_rowsum[row], psum);
            }
        }

        if (blk + 1 < NRB) {
            CP_WAIT0();
            __syncthreads();
        }
    }
}

// ---------------- kernel 2: finalize loss + prec1 ----------------
__global__ void finalize_kernel(float* __restrict__ out, int out_n) {
    __shared__ float sl[B_ROWS];
    __shared__ int   sh[B_ROWS];
    int b = threadIdx.x;
    float s = g_rowsum[b] - NOOR;  // remove the 96 exp2(0)=1 dummy-column terms
    float loss_b = (log2f(s) - g_label_t[b]) * 0.6931471805599453f;
    unsigned int idx = 0xFFFFFFFFu - (unsigned int)(g_rowmax[b] & 0xFFFFFFFFull);
    int lab = g_lbl[b];
    sl[b] = loss_b;
    sh[b] = (idx == (unsigned int)lab) ? 1 : 0;
    __syncthreads();
    for (int st = B_ROWS / 2; st > 0; st >>= 1) {
        if (b < st) { sl[b] += sl[b + st]; sh[b] += sh[b + st]; }
        __syncthreads();
    }
    if (b == 0) {
        out[0] = sl[0] * (1.0f / B_ROWS);
        if (out_n > 1) out[1] = (float)sh[0] * (100.0f / B_ROWS);
    }
}

// ---------------- launch ----------------
extern "C" void kernel_launch(void* const* d_in, const int* in_sizes, int n_in,
                              void* d_out, int out_size) {
    const float* x   = (const float*)d_in[0];
    const float* wgt = (const float*)d_in[1];
    const void*  lab = d_in[2];
    float* out = (float*)d_out;
    (void)in_sizes; (void)n_in;

    cudaFuncSetAttribute(gemm_epi_kernel, cudaFuncAttributeMaxDynamicSharedMemorySize,
                         SMEM_TOTAL);
    cudaFuncSetAttribute(gemm_epi_kernel, cudaFuncAttributePreferredSharedMemoryCarveout,
                         100);

    detect_kernel<<<1, 1024>>>((const int*)lab);
    prep_x_kernel<<<B_ROWS, DIM>>>(x, lab);
    prep_w_kernel<<<(NCLS + 3) / 4, 128>>>(wgt);
    gemm_epi_kernel<<<NT, 256, SMEM_TOTAL>>>();
    finalize_kernel<<<1, B_ROWS>>>(out, out_size);
}

// round 16
// speedup vs baseline: 1.4324x; 1.0727x over previous
#include <cuda_runtime.h>
#include <cuda_bf16.h>
#include <cstdint>

// ---------------- problem constants ----------------
#define B_ROWS 1024
#define DIM    192
#define NCLS   100000

#define TN  128                        // classes per CTA tile
#define RB  64                         // rows per inner block
#define NRB (B_ROWS / RB)              // 16
#define NT  ((NCLS + TN - 1) / TN)     // 782 tiles
#define NOOR ((float)(NT * TN - NCLS)) // 96 out-of-range cols -> each row sum += 96*exp2(0)
#define NKB (DIM / 16)                 // 12 k16-steps
#define STR 200                        // smem row stride in bf16 elems (400B)
#define STRB (STR * 2)                 // 400 bytes

#define S_SCALE 30.0f
#define LOG2E_F 1.4426950408889634f
#define SLOG2E  (S_SCALE * LOG2E_F)
#define COS_M_C 0.98006657784124163f
#define SIN_M_C 0.19866933079506122f
#define TH_C    (-0.98006657784124163f)
#define MM_C    0.039733866159012244f

// ---------------- smem layout (bytes): exactly 76800 -> 3 CTAs/SM ----------------
#define WS_OFF   0                       // W tile: 128 rows x 400B = 51200
#define WS_SZ    (TN * STRB)
#define XS_OFF   (WS_OFF + WS_SZ)        // X block: 64 rows x 400B = 25600 (single buf)
#define XS_SZ    (RB * STRB)
#define SMEM_TOTAL (XS_OFF + XS_SZ)      // 76800

// ---------------- scratch (device globals; no allocation) ----------------
__device__ float              g_rowsum[B_ROWS];
__device__ unsigned long long g_rowmax[B_ROWS];
__device__ float              g_label_t[B_ROWS];
__device__ __nv_bfloat16      g_xbf[B_ROWS * DIM];        // normalized x, bf16
__device__ __nv_bfloat16      g_wbf[(size_t)NCLS * DIM];  // w rounded to bf16
__device__ float              g_ascale[NCLS];             // S*log2e / ||w_bf16||
__device__ int                g_lbl[B_ROWS];              // labels as int32
__device__ int                g_lab64;

// ---------------- helpers ----------------
__device__ __forceinline__ uint32_t smem_u32(const void* p) {
    uint32_t a;
    asm("{ .reg .u64 t; cvta.to.shared.u64 t, %1; cvt.u32.u64 %0, t; }" : "=r"(a) : "l"(p));
    return a;
}
__device__ __forceinline__ float ex2_fast(float x) {   // single MUFU.EX2
    float r;
    asm("ex2.approx.ftz.f32 %0, %1;" : "=f"(r) : "f"(x));
    return r;
}
__device__ __forceinline__ float sqrt_fast(float x) {
    float r;
    asm("sqrt.approx.ftz.f32 %0, %1;" : "=f"(r) : "f"(x));
    return r;
}
#define CP_ASYNC16(dst, src) \
    asm volatile("cp.async.cg.shared.global [%0], [%1], 16;" :: "r"(dst), "l"(src) : "memory")
#define CP_COMMIT() asm volatile("cp.async.commit_group;" ::: "memory")
#define CP_WAIT0()  asm volatile("cp.async.wait_group 0;" ::: "memory")

#define LDSM4(r0, r1, r2, r3, a) \
    asm volatile("ldmatrix.sync.aligned.m8n8.x4.shared.b16 {%0,%1,%2,%3}, [%4];" \
                 : "=r"(r0), "=r"(r1), "=r"(r2), "=r"(r3) : "r"(a))

__device__ __forceinline__ void mma_bf16(float* d, const uint32_t* a, const uint32_t* b) {
    asm volatile(
        "mma.sync.aligned.m16n8k16.row.col.f32.bf16.bf16.f32 "
        "{%0,%1,%2,%3}, {%4,%5,%6,%7}, {%8,%9}, {%0,%1,%2,%3};"
        : "+f"(d[0]), "+f"(d[1]), "+f"(d[2]), "+f"(d[3])
        : "r"(a[0]), "r"(a[1]), "r"(a[2]), "r"(a[3]), "r"(b[0]), "r"(b[1]));
}
__device__ __forceinline__ unsigned int fkey(float v) {
    unsigned int u = __float_as_uint(v);
    return (u & 0x80000000u) ? ~u : (u | 0x80000000u);
}
__device__ __forceinline__ int load_label(const void* lp, int i, int is64) {
    if (is64) return (int)(((const long long*)lp)[i]);
    return ((const int*)lp)[i];
}

// ---------------- kernel 0a: detect label dtype ----------------
__global__ void detect_kernel(const int* __restrict__ lw) {
    __shared__ int any;
    if (threadIdx.x == 0) any = 0;
    __syncthreads();
    int i = threadIdx.x;
    if (i < 512 && lw[2 * i + 1] != 0) atomicOr(&any, 1);
    __syncthreads();
    if (threadIdx.x == 0) g_lab64 = (any == 0) ? 1 : 0;
}

// ---------------- kernel 0b: normalize x -> bf16, labels -> int32, zero scratch ---
__global__ void prep_x_kernel(const float* __restrict__ x, const void* __restrict__ label) {
    int b = blockIdx.x, k = threadIdx.x;  // 192 threads
    float v = x[b * DIM + k];
    float ss = v * v;
    #pragma unroll
    for (int o = 16; o > 0; o >>= 1) ss += __shfl_xor_sync(0xffffffffu, ss, o);
    __shared__ float wp[6];
    __shared__ float inv_s;
    if ((k & 31) == 0) wp[k >> 5] = ss;
    __syncthreads();
    if (k == 0) {
        float t = 0.f;
        #pragma unroll
        for (int i = 0; i < 6; i++) t += wp[i];
        inv_s = 1.0f / fmaxf(sqrtf(t), 1e-12f);
        g_rowsum[b] = 0.f;
        g_rowmax[b] = 0ull;
        g_lbl[b] = load_label(label, b, g_lab64);
    }
    __syncthreads();
    g_xbf[b * DIM + k] = __float2bfloat16(v * inv_s);
}

// ---------------- kernel 0c: w -> bf16 + per-class scale (coalesced float4) ------
__global__ void prep_w_kernel(const float* __restrict__ wgt) {
    int c = blockIdx.x * 4 + (threadIdx.x >> 5);  // 1 class per warp
    int l = threadIdx.x & 31;
    if (c >= NCLS) return;
    const float4* wr4 = (const float4*)(wgt + (size_t)c * DIM);   // 48 float4 per row
    uint2* wo2 = (uint2*)(g_wbf + (size_t)c * DIM);               // 48 uint2 per row
    float ss = 0.f;
    #pragma unroll
    for (int it = 0; it < 2; it++) {
        int j = l + it * 32;
        if (j < 48) {
            float4 v = wr4[j];
            __nv_bfloat162 b0 = __floats2bfloat162_rn(v.x, v.y);
            __nv_bfloat162 b1 = __floats2bfloat162_rn(v.z, v.w);
            float x0 = __bfloat162float(b0.x), x1 = __bfloat162float(b0.y);
            float x2 = __bfloat162float(b1.x), x3 = __bfloat162float(b1.y);
            ss += x0 * x0 + x1 * x1 + x2 * x2 + x3 * x3;
            uint2 o;
            o.x = *(uint32_t*)&b0;
            o.y = *(uint32_t*)&b1;
            wo2[j] = o;
        }
    }
    #pragma unroll
    for (int o = 16; o > 0; o >>= 1) ss += __shfl_xor_sync(0xffffffffu, ss, o);
    if (l == 0) g_ascale[c] = (ss > 0.f) ? SLOG2E * rsqrtf(ss) : 0.f;
}

// ---------------- kernel 1: bf16 HMMA GEMM + fused margin/softmax epilogue --------
__global__ void __launch_bounds__(256, 3)
gemm_epi_kernel() {
    extern __shared__ char smem[];
    const uint32_t sb = smem_u32(smem);
    const int tid = threadIdx.x;
    const int warp = tid >> 5, lane = tid & 31;
    const int c0 = blockIdx.x * TN;

    // W tile + X block 0 via cp.async (24 x 16B chunks per 192-elem row)
    for (int i = tid; i < TN * 24; i += 256) {
        int c = i / 24, j = i % 24;
        int cg = c0 + c; if (cg >= NCLS) cg = NCLS - 1;  // clamp (asv=0 kills OOR cols)
        CP_ASYNC16(sb + WS_OFF + c * STRB + j * 16,
                   (const char*)g_wbf + (size_t)cg * (DIM * 2) + j * 16);
    }
    for (int i = tid; i < RB * 24; i += 256) {
        int r = i / 24, j = i % 24;
        CP_ASYNC16(sb + XS_OFF + r * STRB + j * 16,
                   (const char*)g_xbf + (size_t)r * (DIM * 2) + j * 16);
    }
    CP_COMMIT();

    // warp grid: 2 (rows) x 4 (cols); each warp: 32 rows x 32 cols
    const int wm = warp >> 2, wn = warp & 3;
    const int g = lane >> 2, tig = lane & 3;

    // per-thread class scales (block-invariant): 8 cols; OOR -> 0 so t=0, exp2=1
    // (each row sum gains exactly NOOR=96; finalize subtracts it)
    float asv[4][2];
    #pragma unroll
    for (int ni = 0; ni < 4; ni++)
        #pragma unroll
        for (int q = 0; q < 2; q++) {
            int c = c0 + wn * 32 + ni * 8 + tig * 2 + q;
            asv[ni][q] = (c < NCLS) ? __ldg(&g_ascale[c]) : 0.f;
        }

    // ldmatrix lane address components
    const int a_row = wm * 32 + (lane & 7) + ((lane >> 3) & 1) * 8;
    const uint32_t a_koff = ((lane >> 4) & 1) * 16;  // bytes
    const uint32_t xa0 = sb + XS_OFF + a_row * STRB + a_koff;
    const uint32_t xa1 = xa0 + 16 * STRB;

    const int b_mat = lane >> 3;
    const int b_row = wn * 32 + (b_mat >> 1) * 8 + (lane & 7);
    const uint32_t b_koff = (b_mat & 1) * 16;  // bytes
    uint32_t b_addr[2];
    #pragma unroll
    for (int p = 0; p < 2; p++)
        b_addr[p] = sb + WS_OFF + (b_row + p * 16) * STRB + b_koff;

    CP_WAIT0();
    __syncthreads();

    for (int blk = 0; blk < NRB; blk++) {
        float acc[2][4][4];
        #pragma unroll
        for (int mi = 0; mi < 2; mi++)
            #pragma unroll
            for (int ni = 0; ni < 4; ni++)
                #pragma unroll
                for (int q = 0; q < 4; q++) acc[mi][ni][q] = 0.f;

        #pragma unroll
        for (int kb = 0; kb < NKB; kb++) {
            const uint32_t kadd = kb * 32;  // 16 bf16 = 32 bytes
            uint32_t af[2][4];
            LDSM4(af[0][0], af[0][1], af[0][2], af[0][3], xa0 + kadd);
            LDSM4(af[1][0], af[1][1], af[1][2], af[1][3], xa1 + kadd);
            uint32_t bf[4][2];
            #pragma unroll
            for (int p = 0; p < 2; p++)
                LDSM4(bf[2 * p][0], bf[2 * p][1], bf[2 * p + 1][0], bf[2 * p + 1][1],
                      b_addr[p] + kadd);
            #pragma unroll
            for (int mi = 0; mi < 2; mi++)
                #pragma unroll
                for (int ni = 0; ni < 4; ni++)
                    mma_bf16(acc[mi][ni], af[mi], bf[ni]);
        }

        // all warps done reading X -> start next X load; epilogue overlaps it
        if (blk + 1 < NRB) {
            __syncthreads();
            for (int i = tid; i < RB * 24; i += 256) {
                int r = i / 24, j = i % 24;
                CP_ASYNC16(sb + XS_OFF + r * STRB + j * 16,
                           (const char*)g_xbf + ((size_t)(blk + 1) * RB + r) * (DIM * 2) + j * 16);
            }
            CP_COMMIT();
        }

        // fused epilogue (R12-proven form + split accumulator chains):
        // margin at label col, exp2 partial sum (2 chains), max (2 chains), argmax
        #pragma unroll
        for (int mi = 0; mi < 2; mi++) {
            #pragma unroll
            for (int half = 0; half < 2; half++) {
                int row = blk * RB + wm * 32 + mi * 16 + g + half * 8;
                int lab = __ldg(&g_lbl[row]);
                float ps0 = 0.f, ps1 = 0.f;
                float tmax0 = -1e30f, tmax1 = -1e30f;
                int cmax0 = 0, cmax1 = 0;
                #pragma unroll
                for (int ni = 0; ni < 4; ni++) {
                    #pragma unroll
                    for (int q = 0; q < 2; q++) {
                        int c = c0 + wn * 32 + ni * 8 + tig * 2 + q;
                        float t = acc[mi][ni][half * 2 + q] * asv[ni][q];
                        if (c == lab) {
                            float cs = t * (1.0f / SLOG2E);
                            float sn = sqrt_fast(fmaxf(1.0f - cs * cs, 0.f));
                            float ph = cs * COS_M_C - sn * SIN_M_C;
                            if (!(cs - TH_C > 0.f)) ph = cs - MM_C;
                            t = ph * SLOG2E;
                            g_label_t[row] = t;  // unique writer per row
                        }
                        float e = ex2_fast(t);
                        if (ni < 2) {
                            ps0 += e;
                            if (t > tmax0) { tmax0 = t; cmax0 = c; }
                        } else {
                            ps1 += e;
                            if (t > tmax1) { tmax1 = t; cmax1 = c; }
                        }
                    }
                }
                float psum = ps0 + ps1;
                float tmax = tmax0;
                int cmax = cmax0;
                if (tmax1 > tmax) { tmax = tmax1; cmax = cmax1; }
                psum += __shfl_xor_sync(0xffffffffu, psum, 1);
                psum += __shfl_xor_sync(0xffffffffu, psum, 2);
                unsigned long long key =
                    ((unsigned long long)fkey(tmax) << 32) |
                    (unsigned long long)(0xFFFFFFFFu - (unsigned)cmax);
                unsigned long long o;
                o = __shfl_xor_sync(0xffffffffu, key, 1); key = key > o ? key : o;
                o = __shfl_xor_sync(0xffffffffu, key, 2); key = key > o ? key : o;
                if (tig == 0) {
                    atomicAdd(&g_rowsum[row], psum);
                    atomicMax(&g_rowmax[row], key);
                }
            }
        }

        if (blk + 1 < NRB) {
            CP_WAIT0();
            __syncthreads();
        }
    }
}

// ---------------- kernel 2: finalize loss + prec1 ----------------
__global__ void finalize_kernel(float* __restrict__ out, int out_n) {
    __shared__ float sl[B_ROWS];
    __shared__ int   sh[B_ROWS];
    int b = threadIdx.x;
    float s = g_rowsum[b] - NOOR;  // remove the 96 exp2(0)=1 dummy-column terms
    float loss_b = (log2f(s) - g_label_t[b]) * 0.6931471805599453f;
    unsigned int idx = 0xFFFFFFFFu - (unsigned int)(g_rowmax[b] & 0xFFFFFFFFull);
    int lab = g_lbl[b];
    sl[b] = loss_b;
    sh[b] = (idx == (unsigned int)lab) ? 1 : 0;
    __syncthreads();
    for (int st = B_ROWS / 2; st > 0; st >>= 1) {
        if (b < st) { sl[b] += sl[b + st]; sh[b] += sh[b + st]; }
        __syncthreads();
    }
    if (b == 0) {
        out[0] = sl[0] * (1.0f / B_ROWS);
        if (out_n > 1) out[1] = (float)sh[0] * (100.0f / B_ROWS);
    }
}

// ---------------- launch ----------------
extern "C" void kernel_launch(void* const* d_in, const int* in_sizes, int n_in,
                              void* d_out, int out_size) {
    const float* x   = (const float*)d_in[0];
    const float* wgt = (const float*)d_in[1];
    const void*  lab = d_in[2];
    float* out = (float*)d_out;
    (void)in_sizes; (void)n_in;

    cudaFuncSetAttribute(gemm_epi_kernel, cudaFuncAttributeMaxDynamicSharedMemorySize,
                         SMEM_TOTAL);
    cudaFuncSetAttribute(gemm_epi_kernel, cudaFuncAttributePreferredSharedMemoryCarveout,
                         100);

    detect_kernel<<<1, 1024>>>((const int*)lab);
    prep_x_kernel<<<B_ROWS, DIM>>>(x, lab);
    prep_w_kernel<<<(NCLS + 3) / 4, 128>>>(wgt);
    gemm_epi_kernel<<<NT, 256, SMEM_TOTAL>>>();
    finalize_kernel<<<1, B_ROWS>>>(out, out_size);
}

// round 17
// speedup vs baseline: 1.5262x; 1.0655x over previous
#include <cuda_runtime.h>
#include <cuda_bf16.h>
#include <cstdint>

// ---------------- problem constants ----------------
#define B_ROWS 1024
#define DIM    192
#define NCLS   100000

#define TN  128                        // classes per CTA tile
#define RB  64                         // rows per inner block
#define NRB (B_ROWS / RB)              // 16
#define NT  ((NCLS + TN - 1) / TN)     // 782 tiles
#define NOOR ((float)(NT * TN - NCLS)) // 96 out-of-range cols -> each row sum += 96*exp2(0)
#define NKB (DIM / 16)                 // 12 k16-steps
#define STR 200                        // smem row stride in bf16 elems (400B)
#define STRB (STR * 2)                 // 400 bytes

#define S_SCALE 30.0f
#define LOG2E_F 1.4426950408889634f
#define SLOG2E  (S_SCALE * LOG2E_F)
#define COS_M_C 0.98006657784124163f
#define SIN_M_C 0.19866933079506122f
#define TH_C    (-0.98006657784124163f)
#define MM_C    0.039733866159012244f

// ---------------- smem layout (bytes): exactly 76800 -> 3 CTAs/SM ----------------
#define WS_OFF   0                       // W tile: 128 rows x 400B = 51200
#define WS_SZ    (TN * STRB)
#define XS_OFF   (WS_OFF + WS_SZ)        // X block: 64 rows x 400B = 25600 (single buf)
#define XS_SZ    (RB * STRB)
#define SMEM_TOTAL (XS_OFF + XS_SZ)      // 76800

// ---------------- scratch (device globals; no allocation) ----------------
__device__ float              g_rowsum[B_ROWS];
__device__ unsigned int       g_rowmax32[B_ROWS];  // max exp2(t) bits (positive floats)
__device__ float              g_label_t[B_ROWS];
__device__ __nv_bfloat16      g_xbf[B_ROWS * DIM];        // normalized x, bf16
__device__ __nv_bfloat16      g_wbf[(size_t)NCLS * DIM];  // w rounded to bf16
__device__ float              g_ascale[NCLS];             // S*log2e / ||w_bf16||
__device__ int                g_lbl[B_ROWS];              // labels as int32
__device__ int                g_lab64;

// ---------------- helpers ----------------
__device__ __forceinline__ uint32_t smem_u32(const void* p) {
    uint32_t a;
    asm("{ .reg .u64 t; cvta.to.shared.u64 t, %1; cvt.u32.u64 %0, t; }" : "=r"(a) : "l"(p));
    return a;
}
__device__ __forceinline__ float ex2_fast(float x) {   // single MUFU.EX2
    float r;
    asm("ex2.approx.ftz.f32 %0, %1;" : "=f"(r) : "f"(x));
    return r;
}
__device__ __forceinline__ float sqrt_fast(float x) {
    float r;
    asm("sqrt.approx.ftz.f32 %0, %1;" : "=f"(r) : "f"(x));
    return r;
}
#define CP_ASYNC16(dst, src) \
    asm volatile("cp.async.cg.shared.global [%0], [%1], 16;" :: "r"(dst), "l"(src) : "memory")
#define CP_COMMIT() asm volatile("cp.async.commit_group;" ::: "memory")
#define CP_WAIT0()  asm volatile("cp.async.wait_group 0;" ::: "memory")

#define LDSM4(r0, r1, r2, r3, a) \
    asm volatile("ldmatrix.sync.aligned.m8n8.x4.shared.b16 {%0,%1,%2,%3}, [%4];" \
                 : "=r"(r0), "=r"(r1), "=r"(r2), "=r"(r3) : "r"(a))

__device__ __forceinline__ void mma_bf16(float* d, const uint32_t* a, const uint32_t* b) {
    asm volatile(
        "mma.sync.aligned.m16n8k16.row.col.f32.bf16.bf16.f32 "
        "{%0,%1,%2,%3}, {%4,%5,%6,%7}, {%8,%9}, {%0,%1,%2,%3};"
        : "+f"(d[0]), "+f"(d[1]), "+f"(d[2]), "+f"(d[3])
        : "r"(a[0]), "r"(a[1]), "r"(a[2]), "r"(a[3]), "r"(b[0]), "r"(b[1]));
}
__device__ __forceinline__ int load_label(const void* lp, int i, int is64) {
    if (is64) return (int)(((const long long*)lp)[i]);
    return ((const int*)lp)[i];
}

// ---------------- kernel 0a: detect label dtype ----------------
__global__ void detect_kernel(const int* __restrict__ lw) {
    __shared__ int any;
    if (threadIdx.x == 0) any = 0;
    __syncthreads();
    int i = threadIdx.x;
    if (i < 512 && lw[2 * i + 1] != 0) atomicOr(&any, 1);
    __syncthreads();
    if (threadIdx.x == 0) g_lab64 = (any == 0) ? 1 : 0;
}

// ---------------- kernel 0b: normalize x -> bf16, labels -> int32, zero scratch ---
__global__ void prep_x_kernel(const float* __restrict__ x, const void* __restrict__ label) {
    int b = blockIdx.x, k = threadIdx.x;  // 192 threads
    float v = x[b * DIM + k];
    float ss = v * v;
    #pragma unroll
    for (int o = 16; o > 0; o >>= 1) ss += __shfl_xor_sync(0xffffffffu, ss, o);
    __shared__ float wp[6];
    __shared__ float inv_s;
    if ((k & 31) == 0) wp[k >> 5] = ss;
    __syncthreads();
    if (k == 0) {
        float t = 0.f;
        #pragma unroll
        for (int i = 0; i < 6; i++) t += wp[i];
        inv_s = 1.0f / fmaxf(sqrtf(t), 1e-12f);
        g_rowsum[b] = 0.f;
        g_rowmax32[b] = 0u;
        g_lbl[b] = load_label(label, b, g_lab64);
    }
    __syncthreads();
    g_xbf[b * DIM + k] = __float2bfloat16(v * inv_s);
}

// ---------------- kernel 0c: w -> bf16 + per-class scale (coalesced float4) ------
__global__ void prep_w_kernel(const float* __restrict__ wgt) {
    int c = blockIdx.x * 4 + (threadIdx.x >> 5);  // 1 class per warp
    int l = threadIdx.x & 31;
    if (c >= NCLS) return;
    const float4* wr4 = (const float4*)(wgt + (size_t)c * DIM);   // 48 float4 per row
    uint2* wo2 = (uint2*)(g_wbf + (size_t)c * DIM);               // 48 uint2 per row
    float ss = 0.f;
    #pragma unroll
    for (int it = 0; it < 2; it++) {
        int j = l + it * 32;
        if (j < 48) {
            float4 v = wr4[j];
            __nv_bfloat162 b0 = __floats2bfloat162_rn(v.x, v.y);
            __nv_bfloat162 b1 = __floats2bfloat162_rn(v.z, v.w);
            float x0 = __bfloat162float(b0.x), x1 = __bfloat162float(b0.y);
            float x2 = __bfloat162float(b1.x), x3 = __bfloat162float(b1.y);
            ss += x0 * x0 + x1 * x1 + x2 * x2 + x3 * x3;
            uint2 o;
            o.x = *(uint32_t*)&b0;
            o.y = *(uint32_t*)&b1;
            wo2[j] = o;
        }
    }
    #pragma unroll
    for (int o = 16; o > 0; o >>= 1) ss += __shfl_xor_sync(0xffffffffu, ss, o);
    if (l == 0) g_ascale[c] = (ss > 0.f) ? SLOG2E * rsqrtf(ss) : 0.f;
}

// ---------------- kernel 1: bf16 HMMA GEMM + fused margin/softmax epilogue --------
__global__ void __launch_bounds__(256, 3)
gemm_epi_kernel() {
    extern __shared__ char smem[];
    const uint32_t sb = smem_u32(smem);
    const int tid = threadIdx.x;
    const int warp = tid >> 5, lane = tid & 31;
    const int c0 = blockIdx.x * TN;

    // W tile + X block 0 via cp.async (24 x 16B chunks per 192-elem row)
    for (int i = tid; i < TN * 24; i += 256) {
        int c = i / 24, j = i % 24;
        int cg = c0 + c; if (cg >= NCLS) cg = NCLS - 1;  // clamp (asv=0 kills OOR cols)
        CP_ASYNC16(sb + WS_OFF + c * STRB + j * 16,
                   (const char*)g_wbf + (size_t)cg * (DIM * 2) + j * 16);
    }
    for (int i = tid; i < RB * 24; i += 256) {
        int r = i / 24, j = i % 24;
        CP_ASYNC16(sb + XS_OFF + r * STRB + j * 16,
                   (const char*)g_xbf + (size_t)r * (DIM * 2) + j * 16);
    }
    CP_COMMIT();

    // warp grid: 2 (rows) x 4 (cols); each warp: 32 rows x 32 cols
    const int wm = warp >> 2, wn = warp & 3;
    const int g = lane >> 2, tig = lane & 3;

    // per-thread class scales (block-invariant): 8 cols; OOR -> 0 so t=0, exp2=1
    // (each row sum gains exactly NOOR=96; finalize subtracts it)
    float asv[4][2];
    #pragma unroll
    for (int ni = 0; ni < 4; ni++)
        #pragma unroll
        for (int q = 0; q < 2; q++) {
            int c = c0 + wn * 32 + ni * 8 + tig * 2 + q;
            asv[ni][q] = (c < NCLS) ? __ldg(&g_ascale[c]) : 0.f;
        }

    // ldmatrix lane address components
    const int a_row = wm * 32 + (lane & 7) + ((lane >> 3) & 1) * 8;
    const uint32_t a_koff = ((lane >> 4) & 1) * 16;  // bytes
    const uint32_t xa0 = sb + XS_OFF + a_row * STRB + a_koff;
    const uint32_t xa1 = xa0 + 16 * STRB;

    const int b_mat = lane >> 3;
    const int b_row = wn * 32 + (b_mat >> 1) * 8 + (lane & 7);
    const uint32_t b_koff = (b_mat & 1) * 16;  // bytes
    uint32_t b_addr[2];
    #pragma unroll
    for (int p = 0; p < 2; p++)
        b_addr[p] = sb + WS_OFF + (b_row + p * 16) * STRB + b_koff;

    CP_WAIT0();
    __syncthreads();

    for (int blk = 0; blk < NRB; blk++) {
        float acc[2][4][4];
        #pragma unroll
        for (int mi = 0; mi < 2; mi++)
            #pragma unroll
            for (int ni = 0; ni < 4; ni++)
                #pragma unroll
                for (int q = 0; q < 4; q++) acc[mi][ni][q] = 0.f;

        #pragma unroll
        for (int kb = 0; kb < NKB; kb++) {
            const uint32_t kadd = kb * 32;  // 16 bf16 = 32 bytes
            uint32_t af[2][4];
            LDSM4(af[0][0], af[0][1], af[0][2], af[0][3], xa0 + kadd);
            LDSM4(af[1][0], af[1][1], af[1][2], af[1][3], xa1 + kadd);
            uint32_t bf[4][2];
            #pragma unroll
            for (int p = 0; p < 2; p++)
                LDSM4(bf[2 * p][0], bf[2 * p][1], bf[2 * p + 1][0], bf[2 * p + 1][1],
                      b_addr[p] + kadd);
            #pragma unroll
            for (int mi = 0; mi < 2; mi++)
                #pragma unroll
                for (int ni = 0; ni < 4; ni++)
                    mma_bf16(acc[mi][ni], af[mi], bf[ni]);
        }

        // all warps done reading X -> start next X load; epilogue overlaps it
        if (blk + 1 < NRB) {
            __syncthreads();
            for (int i = tid; i < RB * 24; i += 256) {
                int r = i / 24, j = i % 24;
                CP_ASYNC16(sb + XS_OFF + r * STRB + j * 16,
                           (const char*)g_xbf + ((size_t)(blk + 1) * RB + r) * (DIM * 2) + j * 16);
            }
            CP_COMMIT();
        }

        // fused epilogue: margin at label col (ISETP vs compile-time ni*8+q),
        // exp2 partial sum + max-of-e (single FMNMX; monotone proxy for max logit).
        // No argmax index tracking: prec1 hit test is t_label == max(t), done in
        // finalize via bit-exact ex2 comparison.
        #pragma unroll
        for (int mi = 0; mi < 2; mi++) {
            #pragma unroll
            for (int half = 0; half < 2; half++) {
                int row = blk * RB + wm * 32 + mi * 16 + g + half * 8;
                int lab = __ldg(&g_lbl[row]);
                int rel2 = lab - c0 - wn * 32 - tig * 2;  // == ni*8+q iff lab is ours
                float ps0 = 0.f, ps1 = 0.f;
                float em0 = 0.f, em1 = 0.f;  // e > 0 always, 0 is safe identity
                #pragma unroll
                for (int ni = 0; ni < 4; ni++) {
                    #pragma unroll
                    for (int q = 0; q < 2; q++) {
                        float t = acc[mi][ni][half * 2 + q] * asv[ni][q];
                        if (rel2 == ni * 8 + q) {   // rare: label column
                            float cs = t * (1.0f / SLOG2E);
                            float sn = sqrt_fast(fmaxf(1.0f - cs * cs, 0.f));
                            float ph = cs * COS_M_C - sn * SIN_M_C;
                            if (!(cs - TH_C > 0.f)) ph = cs - MM_C;
                            t = ph * SLOG2E;
                            g_label_t[row] = t;  // unique writer per row
                        }
                        float e = ex2_fast(t);
                        if (ni < 2) { ps0 += e; em0 = fmaxf(em0, e); }
                        else        { ps1 += e; em1 = fmaxf(em1, e); }
                    }
                }
                float psum = ps0 + ps1;
                float emax = fmaxf(em0, em1);
                psum += __shfl_xor_sync(0xffffffffu, psum, 1);
                psum += __shfl_xor_sync(0xffffffffu, psum, 2);
                emax = fmaxf(emax, __shfl_xor_sync(0xffffffffu, emax, 1));
                emax = fmaxf(emax, __shfl_xor_sync(0xffffffffu, emax, 2));
                if (tig == 0) {
                    atomicAdd(&g_rowsum[row], psum);
                    atomicMax(&g_rowmax32[row], __float_as_uint(emax));
                }
            }
        }

        if (blk + 1 < NRB) {
            CP_WAIT0();
            __syncthreads();
        }
    }
}

// ---------------- kernel 2: finalize loss + prec1 ----------------
__global__ void finalize_kernel(float* __restrict__ out, int out_n) {
    __shared__ float sl[B_ROWS];
    __shared__ int   sh[B_ROWS];
    int b = threadIdx.x;
    float s = g_rowsum[b] - NOOR;  // remove the 96 exp2(0)=1 dummy-column terms
    float tl = g_label_t[b];
    float loss_b = (log2f(s) - tl) * 0.6931471805599453f;
    // hit iff label's adjusted logit attains the row max: bit-exact ex2 comparison
    // (same MUFU.EX2 on the same tl bits as in the gemm epilogue).
    float el = ex2_fast(tl);
    sl[b] = loss_b;
    sh[b] = (__float_as_uint(el) == g_rowmax32[b]) ? 1 : 0;
    __syncthreads();
    for (int st = B_ROWS / 2; st > 0; st >>= 1) {
        if (b < st) { sl[b] += sl[b + st]; sh[b] += sh[b + st]; }
        __syncthreads();
    }
    if (b == 0) {
        out[0] = sl[0] * (1.0f / B_ROWS);
        if (out_n > 1) out[1] = (float)sh[0] * (100.0f / B_ROWS);
    }
}

// ---------------- launch ----------------
extern "C" void kernel_launch(void* const* d_in, const int* in_sizes, int n_in,
                              void* d_out, int out_size) {
    const float* x   = (const float*)d_in[0];
    const float* wgt = (const float*)d_in[1];
    const void*  lab = d_in[2];
    float* out = (float*)d_out;
    (void)in_sizes; (void)n_in;

    cudaFuncSetAttribute(gemm_epi_kernel, cudaFuncAttributeMaxDynamicSharedMemorySize,
                         SMEM_TOTAL);
    cudaFuncSetAttribute(gemm_epi_kernel, cudaFuncAttributePreferredSharedMemoryCarveout,
                         100);

    detect_kernel<<<1, 1024>>>((const int*)lab);
    prep_x_kernel<<<B_ROWS, DIM>>>(x, lab);
    prep_w_kernel<<<(NCLS + 3) / 4, 128>>>(wgt);
    gemm_epi_kernel<<<NT, 256, SMEM_TOTAL>>>();
    finalize_kernel<<<1, B_ROWS>>>(out, out_size);
}